// round 1
// baseline (speedup 1.0000x reference)
#include <cuda_runtime.h>
#include <cstdint>

#define SEQ   4096
#define EMB   300
#define K_IN  600      // 2*EMB
#define HID   500
#define JPAD  512      // padded hidden
#define GPAD  2048     // padded gate rows (4*JPAD)
#define NCTA  64       // recurrence CTAs
#define NTHR  1024

// ---------------- scratch (static device globals; no allocation) -----------
__device__ float g_X[(size_t)SEQ * K_IN];          // gathered inputs  [4096][600]
__device__ float g_pre[(size_t)SEQ * GPAD];        // pre-activations  [4096][2048]
__device__ float g_hbuf[2][JPAD];                  // double-buffered h broadcast
__device__ int   g_bar[SEQ];                       // per-step barrier counters

// ---------------- fast activations (MUFU ex2/rcp) --------------------------
__device__ __forceinline__ float fex2(float x){ float y; asm("ex2.approx.f32 %0,%1;":"=f"(y):"f"(x)); return y; }
__device__ __forceinline__ float frcp(float x){ float y; asm("rcp.approx.f32 %0,%1;":"=f"(y):"f"(x)); return y; }
__device__ __forceinline__ float fsig (float x){ return frcp(1.0f + fex2(-1.44269504f * x)); }
__device__ __forceinline__ float ftanh(float x){ float e = fex2(2.88539008f * x); return 1.0f - 2.0f * frcp(e + 1.0f); }

// ---------------- kernel 1: reset per-step barrier counters -----------------
__global__ void k_reset()
{
    for (int i = threadIdx.x; i < SEQ; i += blockDim.x) g_bar[i] = 0;
}

// ---------------- kernel 2: embedding gather + concat -----------------------
// grid 2400 x 1024 == SEQ*K_IN exactly
__global__ void k_gather(const int* __restrict__ words, const int* __restrict__ labels,
                         const float* __restrict__ ew,  const float* __restrict__ ee)
{
    int id = blockIdx.x * blockDim.x + threadIdx.x;
    int t = id / K_IN;
    int k = id - t * K_IN;
    float v = (k < EMB) ? ew[(size_t)words[t]  * EMB + k]
                        : ee[(size_t)labels[t] * EMB + (k - EMB)];
    g_X[id] = v;
}

// ---------------- kernel 3: pre = X @ W_ih^T + (b_ih + b_hh), remapped ------
// Output row R in [0,2048): blk = R>>5 owns 8 hidden units; within blk,
// rl = R&31 = g*8 + uu ; hidden unit j = 8*blk + uu ; W row = g*HID + j.
// Padded (j>=HID) rows are written as 0.
__global__ void __launch_bounds__(256) k_gemm(const float* __restrict__ W,
                                              const float* __restrict__ bi,
                                              const float* __restrict__ bh)
{
    __shared__ float xs[8][64];
    __shared__ float ws[8][68];

    int t0 = blockIdx.x * 64;
    int R0 = blockIdx.y * 64;
    int tid = threadIdx.x;
    int tx = tid & 15;        // t sub-index
    int ty = tid >> 4;        // r sub-index

    float acc[4][4];
#pragma unroll
    for (int i = 0; i < 4; i++)
#pragma unroll
        for (int j = 0; j < 4; j++) acc[i][j] = 0.0f;

    for (int k0 = 0; k0 < K_IN; k0 += 8) {
#pragma unroll
        for (int p = 0; p < 2; p++) {
            int e  = tid + p * 256;     // 512 elements total per tile
            int kk = e >> 6;
            int rr = e & 63;
            // W tile (with row remap)
            int R = R0 + rr;
            int g = (R >> 3) & 3;
            int j = ((R >> 5) << 3) | (R & 7);
            float wv = 0.0f;
            if (j < HID) wv = W[(size_t)(g * HID + j) * K_IN + (k0 + kk)];
            ws[kk][rr] = wv;
            // X tile
            xs[kk][rr] = g_X[(size_t)(t0 + rr) * K_IN + (k0 + kk)];
        }
        __syncthreads();
#pragma unroll
        for (int kk = 0; kk < 8; kk++) {
            float a[4], x[4];
#pragma unroll
            for (int i = 0; i < 4; i++) a[i] = ws[kk][ty + 16 * i];
#pragma unroll
            for (int j = 0; j < 4; j++) x[j] = xs[kk][tx + 16 * j];
#pragma unroll
            for (int i = 0; i < 4; i++)
#pragma unroll
                for (int j = 0; j < 4; j++) acc[i][j] += a[i] * x[j];
        }
        __syncthreads();
    }

#pragma unroll
    for (int i = 0; i < 4; i++) {
        int R = R0 + ty + 16 * i;
        int g = (R >> 3) & 3;
        int j = ((R >> 5) << 3) | (R & 7);
        bool valid = (j < HID);
        float bb = valid ? (bi[g * HID + j] + bh[g * HID + j]) : 0.0f;
#pragma unroll
        for (int jx = 0; jx < 4; jx++) {
            int t = t0 + tx + 16 * jx;
            g_pre[(size_t)t * GPAD + R] = valid ? (acc[i][jx] + bb) : 0.0f;
        }
    }
}

// ---------------- kernel 4: persistent LSTM recurrence + final FC -----------
// 64 CTAs x 1024 threads. CTA blk owns hidden units [8*blk, 8*blk+8).
// Warp w (0..31) computes gate row rl = w = g*8 + uu (g = w>>3, uu = w&7).
// Lane covers k = lane + 32*m, m<16 -> 16 register-resident W_hh weights.
__global__ void __launch_bounds__(NTHR, 1)
k_lstm(const float* __restrict__ Whh, const float* __restrict__ fcw,
       const float* __restrict__ fcb, float* __restrict__ out)
{
    __shared__ float sh_h[JPAD];
    __shared__ float sgate[32];

    const int tid  = threadIdx.x;
    const int blk  = blockIdx.x;
    const int w    = tid >> 5;
    const int lane = tid & 31;
    const int g    = w >> 3;
    const int uu   = w & 7;
    const int j    = blk * 8 + uu;
    const int wrow = g * HID + j;

    // load W_hh slice into registers (zeros for padding)
    float wreg[16];
#pragma unroll
    for (int m = 0; m < 16; m++) {
        int k = lane + 32 * m;
        wreg[m] = (j < HID && k < HID) ? Whh[(size_t)wrow * HID + k] : 0.0f;
    }

    if (tid < JPAD) sh_h[tid] = 0.0f;   // h(0) = 0
    float c = 0.0f;                     // cell state, meaningful for tid < 8
    __syncthreads();

    const float* preB = g_pre + (size_t)blk * 32;

#pragma unroll 1
    for (int t = 0; t < SEQ; t++) {
        // pre value for this warp's gate row (uniform across warp -> 1 request)
        float pv = __ldg(&preB[(size_t)t * GPAD + w]);

        // matvec: gate partial over register weights, h from smem (stride-32,
        // conflict-free: 32 lanes hit 32 distinct banks)
        float acc = 0.0f;
#pragma unroll
        for (int m = 0; m < 16; m++) acc += wreg[m] * sh_h[lane + 32 * m];
        acc += __shfl_xor_sync(0xffffffffu, acc, 16);
        acc += __shfl_xor_sync(0xffffffffu, acc, 8);
        acc += __shfl_xor_sync(0xffffffffu, acc, 4);
        acc += __shfl_xor_sync(0xffffffffu, acc, 2);
        acc += __shfl_xor_sync(0xffffffffu, acc, 1);

        if (lane == 0) {
            float x = acc + pv;
            sgate[w] = (g == 2) ? ftanh(x) : fsig(x);
        }
        __syncthreads();

        const int nb = (t + 1) & 1;
        if (tid < 8) {
            float gi = sgate[tid];
            float gf = sgate[8 + tid];
            float gg = sgate[16 + tid];
            float go = sgate[24 + tid];
            c = gf * c + gi * gg;
            float h = go * ftanh(c);
            g_hbuf[nb][blk * 8 + tid] = h;
        }
        __syncthreads();

        // inter-CTA barrier for step t (counters pre-zeroed by k_reset)
        if (tid == 0) {
            __threadfence();                       // release h slice
            atomicAdd(&g_bar[t], 1);               // RED (result unused)
            while (*(volatile int*)&g_bar[t] < NCTA) { }
            __threadfence();                       // acquire
        }
        __syncthreads();

        // fetch full h(t+1); MUST bypass L1 (not coherent across SMs)
        if (tid < JPAD) sh_h[tid] = __ldcg(&g_hbuf[nb][tid]);
        __syncthreads();
    }

    // final FC: out[20] = fc_w @ h_last + fc_b   (CTA 0 only, one warp/output)
    if (blk == 0 && w < 20) {
        float a = 0.0f;
#pragma unroll
        for (int m = 0; m < 16; m++) {
            int k = lane + 32 * m;
            if (k < HID) a += fcw[(size_t)w * HID + k] * sh_h[k];
        }
        a += __shfl_xor_sync(0xffffffffu, a, 16);
        a += __shfl_xor_sync(0xffffffffu, a, 8);
        a += __shfl_xor_sync(0xffffffffu, a, 4);
        a += __shfl_xor_sync(0xffffffffu, a, 2);
        a += __shfl_xor_sync(0xffffffffu, a, 1);
        if (lane == 0) out[w] = a + fcb[w];
    }
}

// ---------------- launch ----------------------------------------------------
extern "C" void kernel_launch(void* const* d_in, const int* in_sizes, int n_in,
                              void* d_out, int out_size)
{
    const int*   words  = (const int*)  d_in[0];
    const int*   labels = (const int*)  d_in[1];
    const float* ew     = (const float*)d_in[2];
    const float* ee     = (const float*)d_in[3];
    const float* W_ih   = (const float*)d_in[4];
    const float* W_hh   = (const float*)d_in[5];
    const float* b_ih   = (const float*)d_in[6];
    const float* b_hh   = (const float*)d_in[7];
    const float* fc_w   = (const float*)d_in[8];
    const float* fc_b   = (const float*)d_in[9];
    float* out = (float*)d_out;

    k_reset<<<1, 256>>>();
    k_gather<<<(SEQ * K_IN) / 1024, 1024>>>(words, labels, ew, ee);
    k_gemm<<<dim3(SEQ / 64, GPAD / 64), 256>>>(W_ih, b_ih, b_hh);
    k_lstm<<<NCTA, NTHR>>>(W_hh, fc_w, fc_b, out);
}